// round 4
// baseline (speedup 1.0000x reference)
#include <cuda_runtime.h>

// Per-box preprocessed params: cx, cy, cos, sin, hx, hy, pad, pad  (8 floats)
#define MAXB 8192
__device__ float g_params[MAXB * 8];

__global__ void prep_kernel(const float* __restrict__ boxes, int nb) {
    int i = blockIdx.x * blockDim.x + threadIdx.x;
    if (i >= nb) return;
    float cx = boxes[i * 5 + 0];
    float cy = boxes[i * 5 + 1];
    float hx = boxes[i * 5 + 2] * 0.5f;
    float hy = boxes[i * 5 + 3] * 0.5f;
    float ang = boxes[i * 5 + 4];
    float s, c;
    sincosf(ang, &s, &c);
    float4* p = reinterpret_cast<float4*>(&g_params[i * 8]);
    p[0] = make_float4(cx, cy, c, s);
    p[1] = make_float4(hx, hy, 0.0f, 0.0f);
}

// 1-D GIoU of [-r1, r1] vs [t-r2, t+r2] with t = |q|.
// inter_pre = min(2r1, 2r2, r1+r2-t);  inter_pre + hull = 2(r1+r2)
// g = inter/uni - (hull-uni)/hull = (uni*(uni-hull) + inter*hull)/(uni*hull)
// and uni - hull = min(inter_pre, 0).
__device__ __forceinline__ float giou_axis(float r1, float r2, float q) {
    float u   = r1 + r2;
    float v   = u - fabsf(q);          // FADD with |src| modifier
    float mn  = fminf(r1, r2);
    float m   = fminf(mn + mn, v);     // inter (pre-clamp)
    float inter = fmaxf(m, 0.0f);
    float neg   = fminf(m, 0.0f);      // uni - hull
    float u2  = u + u;
    float hull = u2 - m;
    float uni  = u2 - inter;
    float num  = fmaf(uni, neg, inter * hull);
    return num * __fdividef(1.0f, uni * hull);
}

#define TILE 64

__global__ __launch_bounds__(256) void pair_kernel(float* __restrict__ out, int nb, int T) {
    // Map linear block index -> upper-triangular tile pair (r <= c)
    const int b = blockIdx.x;
    int r = (int)((2.0f * T + 1.0f -
                   sqrtf((2.0f * T + 1.0f) * (2.0f * T + 1.0f) - 8.0f * (float)b)) * 0.5f);
    if (r < 0) r = 0;
    if (r > T - 1) r = T - 1;
    while (r > 0 && r * T - (r * (r - 1)) / 2 > b) --r;
    while ((r + 1) * T - ((r + 1) * r) / 2 <= b) ++r;
    const int c = r + (b - (r * T - (r * (r - 1)) / 2));

    const int i0 = r * TILE;
    const int j0 = c * TILE;
    const int tid = threadIdx.x;

    __shared__ float sp[2][TILE][8];

    // Cooperative load: 2 tiles * 64 boxes * 2 float4 = 256 float4 loads
    {
        int which = tid >> 7;          // 0 -> i tile, 1 -> j tile
        int slot  = (tid >> 1) & 63;
        int half  = tid & 1;
        int gidx  = (which ? j0 : i0) + slot;
        float4 v = make_float4(0.0f, 0.0f, 1.0f, 0.0f);
        if (gidx < nb)
            v = reinterpret_cast<const float4*>(g_params)[gidx * 2 + half];
        reinterpret_cast<float4*>(&sp[which][slot][0])[half] = v;
    }
    __syncthreads();

    const int tx = tid & 15;   // j sub-tile
    const int ty = tid >> 4;   // i sub-tile
    const int ib = ty * 4;
    const int jb = tx * 4;

    // Hoist the 4 j-box params into registers
    float cxj[4], cyj[4], cj[4], sj[4], hxj[4], hyj[4];
#pragma unroll
    for (int jj = 0; jj < 4; jj++) {
        const float* q = &sp[1][jb + jj][0];
        cxj[jj] = q[0]; cyj[jj] = q[1];
        cj[jj]  = q[2]; sj[jj]  = q[3];
        hxj[jj] = q[4]; hyj[jj] = q[5];
    }

    float res[4][4];

#pragma unroll
    for (int ii = 0; ii < 4; ii++) {
        const float* p = &sp[0][ib + ii][0];
        const float cxi = p[0], cyi = p[1];
        const float ci  = p[2], si  = p[3];
        const float hxi = p[4], hyi = p[5];

#pragma unroll
        for (int jj = 0; jj < 4; jj++) {
            const float dx = cxj[jj] - cxi;
            const float dy = cyj[jj] - cyi;
            // cos/sin of angle difference
            const float cd = fmaf(ci, cj[jj], si * sj[jj]);
            const float sd = fmaf(si, cj[jj], -(ci * sj[jj]));
            const float A  = fabsf(cd);
            const float Bb = fabsf(sd);
            // center-delta projections on the 4 unit axes (abs folded in giou_axis)
            const float q1 = fmaf(dx, ci, -(dy * si));
            const float q2 = fmaf(dx, si, dy * ci);
            const float q3 = fmaf(dx, cj[jj], -(dy * sj[jj]));
            const float q4 = fmaf(dx, sj[jj], dy * cj[jj]);
            // other-box radii on each axis
            const float r21 = fmaf(hxj[jj], A,  hyj[jj] * Bb);
            const float r22 = fmaf(hxj[jj], Bb, hyj[jj] * A);
            const float r23 = fmaf(hxi,     A,  hyi * Bb);
            const float r24 = fmaf(hxi,     Bb, hyi * A);

            float g1 = giou_axis(hxi,     r21, q1);
            float g2 = giou_axis(hyi,     r22, q2);
            float g3 = giou_axis(hxj[jj], r23, q3);
            float g4 = giou_axis(hyj[jj], r24, q4);

            float g = fminf(fminf(g1, g2), fminf(g3, g4));
            res[ii][jj] = fmaxf(g, 0.0f);
        }
    }

    // Zero the diagonal (only diagonal blocks pay for this)
    if (i0 == j0) {
#pragma unroll
        for (int ii = 0; ii < 4; ii++)
#pragma unroll
            for (int jj = 0; jj < 4; jj++)
                if (ib + ii == jb + jj) res[ii][jj] = 0.0f;
    }

    const bool full = (i0 + TILE <= nb) && (j0 + TILE <= nb);

    // Direct store: rows i0+ib.., cols j0+jb..
    if (full) {
#pragma unroll
        for (int ii = 0; ii < 4; ii++) {
            float4 v = make_float4(res[ii][0], res[ii][1], res[ii][2], res[ii][3]);
            *reinterpret_cast<float4*>(&out[(size_t)(i0 + ib + ii) * nb + j0 + jb]) = v;
        }
        if (i0 != j0) {
            // Transposed store: rows j0+jb.., cols i0+ib..
#pragma unroll
            for (int jj = 0; jj < 4; jj++) {
                float4 v = make_float4(res[0][jj], res[1][jj], res[2][jj], res[3][jj]);
                *reinterpret_cast<float4*>(&out[(size_t)(j0 + jb + jj) * nb + i0 + ib]) = v;
            }
        }
    } else {
#pragma unroll
        for (int ii = 0; ii < 4; ii++) {
            int gi = i0 + ib + ii;
            if (gi >= nb) continue;
#pragma unroll
            for (int jj = 0; jj < 4; jj++) {
                int gj = j0 + jb + jj;
                if (gj < nb) out[(size_t)gi * nb + gj] = res[ii][jj];
            }
        }
        if (i0 != j0) {
#pragma unroll
            for (int jj = 0; jj < 4; jj++) {
                int gj = j0 + jb + jj;
                if (gj >= nb) continue;
#pragma unroll
                for (int ii = 0; ii < 4; ii++) {
                    int gi = i0 + ib + ii;
                    if (gi < nb) out[(size_t)gj * nb + gi] = res[ii][jj];
                }
            }
        }
    }
}

extern "C" void kernel_launch(void* const* d_in, const int* in_sizes, int n_in,
                              void* d_out, int out_size) {
    const float* boxes = (const float*)d_in[0];
    float* out = (float*)d_out;
    const int nb = in_sizes[0] / 5;

    prep_kernel<<<(nb + 255) / 256, 256>>>(boxes, nb);

    const int T = (nb + TILE - 1) / TILE;
    const int nblk = T * (T + 1) / 2;
    pair_kernel<<<nblk, 256>>>(out, nb, T);
}

// round 5
// speedup vs baseline: 1.2884x; 1.2884x over previous
#include <cuda_runtime.h>

// Per-box preprocessed params: cx, cy, cos, sin, hx, hy, pad, pad  (8 floats)
#define MAXB 8192
__device__ float g_params[MAXB * 8];

__global__ void prep_kernel(const float* __restrict__ boxes, int nb) {
    int i = blockIdx.x * blockDim.x + threadIdx.x;
    if (i >= nb) return;
    float cx = boxes[i * 5 + 0];
    float cy = boxes[i * 5 + 1];
    float hx = boxes[i * 5 + 2] * 0.5f;
    float hy = boxes[i * 5 + 3] * 0.5f;
    float ang = boxes[i * 5 + 4];
    float s, c;
    sincosf(ang, &s, &c);
    float4* p = reinterpret_cast<float4*>(&g_params[i * 8]);
    p[0] = make_float4(cx, cy, c, s);
    p[1] = make_float4(hx, hy, 0.0f, 0.0f);
}

// 1-D GIoU of [-r1, r1] vs [d-r2, d+r2], d = |q| — closed form.
// All three regimes (separated / partial overlap / containment) collapse to:
//   a = r1+r2;  o = a - d;  m = min(2*min(r1,r2), o);  g = m / (2a - m)
__device__ __forceinline__ float giou_axis(float r1, float r2, float q) {
    float a  = r1 + r2;
    float o  = a - fabsf(q);             // FADD with |src| modifier
    float mn = fminf(r1, r2);            // FMNMX (alu)
    float m  = fminf(mn + mn, o);        // FADD + FMNMX
    float den = fmaf(a, 2.0f, -m);       // FFMA with immediate
    return __fdividef(m, den);           // MUFU.RCP + FMUL
}

#define TILE 64

__global__ __launch_bounds__(256) void pair_kernel(float* __restrict__ out, int nb) {
    // sp[0] = i-tile boxes, sp[1] = j-tile boxes; 8 floats each
    __shared__ float sp[2][TILE][8];

    const int i0 = blockIdx.y * TILE;
    const int j0 = blockIdx.x * TILE;
    const int tid = threadIdx.x;

    // Cooperative load: 2 tiles * 64 boxes * 2 float4 = 256 float4 loads
    {
        int which = tid >> 7;          // 0 -> i tile, 1 -> j tile
        int slot  = (tid >> 1) & 63;   // box within tile
        int half  = tid & 1;           // which float4 of the 8-float record
        int gidx  = (which ? j0 : i0) + slot;
        float4 v = make_float4(0.0f, 0.0f, 1.0f, 0.0f);
        if (gidx < nb)
            v = reinterpret_cast<const float4*>(g_params)[gidx * 2 + half];
        reinterpret_cast<float4*>(&sp[which][slot][0])[half] = v;
    }
    __syncthreads();

    const int tx = tid & 15;   // j sub-tile (4 boxes each)
    const int ty = tid >> 4;   // i sub-tile (4 boxes each)
    const int ib = ty * 4;
    const int jb = tx * 4;

    // Hoist the 4 j-box params into registers
    float cxj[4], cyj[4], cj[4], sj[4], hxj[4], hyj[4];
#pragma unroll
    for (int jj = 0; jj < 4; jj++) {
        const float* q = &sp[1][jb + jj][0];
        cxj[jj] = q[0]; cyj[jj] = q[1];
        cj[jj]  = q[2]; sj[jj]  = q[3];
        hxj[jj] = q[4]; hyj[jj] = q[5];
    }

#pragma unroll
    for (int ii = 0; ii < 4; ii++) {
        const float* p = &sp[0][ib + ii][0];
        const float cxi = p[0], cyi = p[1];
        const float ci  = p[2], si  = p[3];
        const float hxi = p[4], hyi = p[5];
        const int gi = i0 + ib + ii;

        float4 res;
        float* resf = &res.x;
#pragma unroll
        for (int jj = 0; jj < 4; jj++) {
            const float dx = cxj[jj] - cxi;
            const float dy = cyj[jj] - cyi;
            // cos/sin of angle difference
            const float cd = fmaf(ci, cj[jj], si * sj[jj]);
            const float sd = fmaf(si, cj[jj], -(ci * sj[jj]));
            const float A  = fabsf(cd);
            const float Bb = fabsf(sd);
            // center-delta projections on the 4 unit axes (|.| folded in giou_axis)
            const float q1 = fmaf(dx, ci, -(dy * si));
            const float q2 = fmaf(dx, si, dy * ci);
            const float q3 = fmaf(dx, cj[jj], -(dy * sj[jj]));
            const float q4 = fmaf(dx, sj[jj], dy * cj[jj]);
            // other-box radii on each axis
            const float r21 = fmaf(hxj[jj], A,  hyj[jj] * Bb);
            const float r22 = fmaf(hxj[jj], Bb, hyj[jj] * A);
            const float r23 = fmaf(hxi,     A,  hyi * Bb);
            const float r24 = fmaf(hxi,     Bb, hyi * A);

            float g1 = giou_axis(hxi,     r21, q1);
            float g2 = giou_axis(hyi,     r22, q2);
            float g3 = giou_axis(hxj[jj], r23, q3);
            float g4 = giou_axis(hyj[jj], r24, q4);

            float g = fminf(fminf(g1, g2), fminf(g3, g4));
            g = fmaxf(g, 0.0f);
            const int gj = j0 + jb + jj;
            if (gi == gj) g = 0.0f;
            resf[jj] = g;
        }

        const int gjbase = j0 + jb;
        if (gi < nb && gjbase + 3 < nb) {
            *reinterpret_cast<float4*>(&out[(size_t)gi * nb + gjbase]) = res;
        } else if (gi < nb) {
#pragma unroll
            for (int jj = 0; jj < 4; jj++)
                if (gjbase + jj < nb) out[(size_t)gi * nb + gjbase + jj] = resf[jj];
        }
    }
}

extern "C" void kernel_launch(void* const* d_in, const int* in_sizes, int n_in,
                              void* d_out, int out_size) {
    const float* boxes = (const float*)d_in[0];
    float* out = (float*)d_out;
    const int nb = in_sizes[0] / 5;

    prep_kernel<<<(nb + 255) / 256, 256>>>(boxes, nb);

    dim3 grid((nb + TILE - 1) / TILE, (nb + TILE - 1) / TILE);
    pair_kernel<<<grid, 256>>>(out, nb);
}

// round 6
// speedup vs baseline: 1.5854x; 1.2305x over previous
#include <cuda_runtime.h>

// Per-box preprocessed params: cx, cy, cos, sin, hx, hy, pad, pad  (8 floats)
#define MAXB 8192
__device__ float g_params[MAXB * 8];

__global__ void prep_kernel(const float* __restrict__ boxes, int nb) {
    int i = blockIdx.x * blockDim.x + threadIdx.x;
    if (i >= nb) return;
    float cx = boxes[i * 5 + 0];
    float cy = boxes[i * 5 + 1];
    float hx = boxes[i * 5 + 2] * 0.5f;
    float hy = boxes[i * 5 + 3] * 0.5f;
    float ang = boxes[i * 5 + 4];
    float s, c;
    sincosf(ang, &s, &c);
    float4* p = reinterpret_cast<float4*>(&g_params[i * 8]);
    p[0] = make_float4(cx, cy, c, s);
    p[1] = make_float4(hx, hy, 0.0f, 0.0f);
}

// 1-D GIoU of [-r1, r1] vs [d-r2, d+r2], d = |q| — closed form.
//   a = r1+r2;  o = a - d;  m = min(2*min(r1,r2), o);  g = m / (2a - m)
__device__ __forceinline__ float giou_axis(float r1, float r2, float q) {
    float a  = r1 + r2;
    float o  = a - fabsf(q);
    float mn = fminf(r1, r2);
    float m  = fminf(mn + mn, o);
    float den = fmaf(a, 2.0f, -m);
    return __fdividef(m, den);
}

#define TILE 64

__global__ __launch_bounds__(256) void pair_kernel(float* __restrict__ out, int nb) {
    // SoA shared layout: index [0,64) = i-tile, [64,128) = j-tile.
    // 16B-aligned so the j-hoist can use LDS.128 at 16B stride (2-way max).
    __shared__ __align__(16) float s_cx[128];
    __shared__ __align__(16) float s_cy[128];
    __shared__ __align__(16) float s_c [128];
    __shared__ __align__(16) float s_s [128];
    __shared__ __align__(16) float s_hx[128];
    __shared__ __align__(16) float s_hy[128];

    const int i0 = blockIdx.y * TILE;
    const int j0 = blockIdx.x * TILE;
    const int tid = threadIdx.x;

    // Cooperative load: 128 boxes * 2 float4 reads = 256, one per thread,
    // scattered into SoA.
    {
        int which = tid >> 7;          // 0 -> i tile, 1 -> j tile
        int slot  = (tid >> 1) & 63;   // box within tile
        int half  = tid & 1;           // which float4 of the 8-float record
        int gidx  = (which ? j0 : i0) + slot;
        float4 v = half ? make_float4(1.0f, 1.0f, 0.0f, 0.0f)
                        : make_float4(0.0f, 0.0f, 1.0f, 0.0f);
        if (gidx < nb)
            v = reinterpret_cast<const float4*>(g_params)[gidx * 2 + half];
        int d = which * 64 + slot;
        if (half == 0) {
            s_cx[d] = v.x; s_cy[d] = v.y; s_c[d] = v.z; s_s[d] = v.w;
        } else {
            s_hx[d] = v.x; s_hy[d] = v.y;
        }
    }
    __syncthreads();

    const int tx = tid & 15;   // j sub-tile (4 boxes each)
    const int ty = tid >> 4;   // i sub-tile (4 boxes each)
    const int ib = ty * 4;
    const int jb = tx * 4;

    // Hoist the 4 j-box params via vectorized LDS.128 from SoA
    float4 CXJ = *reinterpret_cast<const float4*>(&s_cx[64 + jb]);
    float4 CYJ = *reinterpret_cast<const float4*>(&s_cy[64 + jb]);
    float4 CJ4 = *reinterpret_cast<const float4*>(&s_c [64 + jb]);
    float4 SJ4 = *reinterpret_cast<const float4*>(&s_s [64 + jb]);
    float4 HXJ = *reinterpret_cast<const float4*>(&s_hx[64 + jb]);
    float4 HYJ = *reinterpret_cast<const float4*>(&s_hy[64 + jb]);
    const float* cxj = &CXJ.x;
    const float* cyj = &CYJ.x;
    const float* cj  = &CJ4.x;
    const float* sj  = &SJ4.x;
    const float* hxj = &HXJ.x;
    const float* hyj = &HYJ.x;

    const bool diagblk = (i0 == j0);

#pragma unroll
    for (int ii = 0; ii < 4; ii++) {
        // i-box params: broadcast scalar LDS (conflict-free)
        const float cxi = s_cx[ib + ii];
        const float cyi = s_cy[ib + ii];
        const float ci  = s_c [ib + ii];
        const float si  = s_s [ib + ii];
        const float hxi = s_hx[ib + ii];
        const float hyi = s_hy[ib + ii];
        const int gi = i0 + ib + ii;

        float4 res;
        float* resf = &res.x;
#pragma unroll
        for (int jj = 0; jj < 4; jj++) {
            const float dx = cxj[jj] - cxi;
            const float dy = cyj[jj] - cyi;
            // cos/sin of angle difference
            const float cd = fmaf(ci, cj[jj], si * sj[jj]);
            const float sd = fmaf(si, cj[jj], -(ci * sj[jj]));
            const float A  = fabsf(cd);
            const float Bb = fabsf(sd);
            // center-delta projections on the 4 unit axes (|.| folded in giou_axis)
            const float q1 = fmaf(dx, ci, -(dy * si));
            const float q2 = fmaf(dx, si, dy * ci);
            const float q3 = fmaf(dx, cj[jj], -(dy * sj[jj]));
            const float q4 = fmaf(dx, sj[jj], dy * cj[jj]);
            // other-box radii on each axis
            const float r21 = fmaf(hxj[jj], A,  hyj[jj] * Bb);
            const float r22 = fmaf(hxj[jj], Bb, hyj[jj] * A);
            const float r23 = fmaf(hxi,     A,  hyi * Bb);
            const float r24 = fmaf(hxi,     Bb, hyi * A);

            float g1 = giou_axis(hxi,     r21, q1);
            float g2 = giou_axis(hyi,     r22, q2);
            float g3 = giou_axis(hxj[jj], r23, q3);
            float g4 = giou_axis(hyj[jj], r24, q4);

            float g = fminf(fminf(g1, g2), fminf(g3, g4));
            resf[jj] = fmaxf(g, 0.0f);
        }

        // Diagonal fixup: uniform branch, only 64 of 4096 blocks take it
        if (diagblk) {
            int dj = (ib + ii) - jb;
            if (dj >= 0 && dj < 4) resf[dj] = 0.0f;
        }

        const int gjbase = j0 + jb;
        if (gi < nb && gjbase + 3 < nb) {
            *reinterpret_cast<float4*>(&out[(size_t)gi * nb + gjbase]) = res;
        } else if (gi < nb) {
#pragma unroll
            for (int jj = 0; jj < 4; jj++)
                if (gjbase + jj < nb) out[(size_t)gi * nb + gjbase + jj] = resf[jj];
        }
    }
}

extern "C" void kernel_launch(void* const* d_in, const int* in_sizes, int n_in,
                              void* d_out, int out_size) {
    const float* boxes = (const float*)d_in[0];
    float* out = (float*)d_out;
    const int nb = in_sizes[0] / 5;

    prep_kernel<<<(nb + 255) / 256, 256>>>(boxes, nb);

    dim3 grid((nb + TILE - 1) / TILE, (nb + TILE - 1) / TILE);
    pair_kernel<<<grid, 256>>>(out, nb);
}